// round 8
// baseline (speedup 1.0000x reference)
#include <cuda_runtime.h>

// DenseDilatedKnnGraph: x (4,64,8192,1) fp32 -> edge_index (2,4,8192,9)
// k=9, dilation=1 (fixed by setup_inputs).
//
// OUTPUT STORED AS FLOAT32: evidence across rounds —
//   int32 stores  -> rc=0, rel_err == 1.000000 exactly (values read as float
//                    denormals ~0 -> ||0-ref||/||ref|| = 1)
//   int64 stores  -> illegal memory access (buffer is 589824 * 4 bytes)
// => harness d_out is float32; indices <= 8191 are exactly representable.
//
// Stage 1: L2-normalize over D, transpose to point-major [B][N][D], store sq.
// Stage 2: all-pairs d2 = sq_n + sq_m - 2*dot, per-row top-9 smallest with
//          stable tie-break (lower index first). sqrt is monotone -> rank on
//          clamped d2 directly.

#define BB 4
#define DD 64
#define NN 8192
#define KK 9
#define TS 128      // candidates per smem tile
#define ROWS 64     // query rows per CTA (= threads per CTA)

// scratch (no cudaMalloc allowed)
__device__ __align__(16) float g_pts[(size_t)BB * NN * DD];   // 8 MB normalized points
__device__ float g_sq[BB * NN];

// ---------------------------------------------------------------------------
// Stage 1: normalize + transpose. One thread per point (b, n).
// x layout: x[b*D*N + d*N + n]  (coalesced over n)
// ---------------------------------------------------------------------------
__global__ void __launch_bounds__(256) normalize_kernel(const float* __restrict__ x) {
    int idx = blockIdx.x * blockDim.x + threadIdx.x;
    if (idx >= BB * NN) return;
    int b = idx / NN;
    int n = idx - b * NN;
    const float* xb = x + (size_t)b * DD * NN + n;

    float v[DD];
    float s = 0.0f;
#pragma unroll
    for (int d = 0; d < DD; d++) {
        v[d] = xb[(size_t)d * NN];
        s += v[d] * v[d];
    }
    float nrm = fmaxf(sqrtf(s), 1e-12f);   // F.normalize eps
    float s2 = 0.0f;
#pragma unroll
    for (int d = 0; d < DD; d++) {
        float xn = v[d] / nrm;             // true division, match reference
        v[d] = xn;
        s2 += xn * xn;                     // reference recomputes sq from normalized pts
    }
    float4* dst = (float4*)(g_pts + (size_t)idx * DD);
#pragma unroll
    for (int d = 0; d < DD / 4; d++)
        dst[d] = make_float4(v[4 * d], v[4 * d + 1], v[4 * d + 2], v[4 * d + 3]);
    g_sq[idx] = s2;
}

// ---------------------------------------------------------------------------
// Stage 2: brute-force KNN. One thread per query row; CTA streams candidate
// tiles through smem (warp-broadcast LDS.128, conflict-free). Scalar FFMA.
// ---------------------------------------------------------------------------
__global__ void __launch_bounds__(ROWS) knn_kernel(float* __restrict__ out) {
    __shared__ __align__(16) float sh[TS * DD];   // 32 KB
    __shared__ float shsq[TS];

    const int tile = blockIdx.x;                  // 0 .. B*N/ROWS - 1
    const int b = tile / (NN / ROWS);
    const int row = (tile - b * (NN / ROWS)) * ROWS + threadIdx.x;
    const size_t base = (size_t)b * NN;

    // query point -> 16 float4 registers
    float4 q[DD / 4];
    {
        const float4* qp = (const float4*)(g_pts + (base + row) * DD);
#pragma unroll
        for (int i = 0; i < DD / 4; i++) q[i] = qp[i];
    }
    const float sqn = g_sq[base + row];

    float bd[KK];
    int   bi[KK];
#pragma unroll
    for (int i = 0; i < KK; i++) { bd[i] = 3.4e38f; bi[i] = 0; }

    for (int t0 = 0; t0 < NN; t0 += TS) {
        __syncthreads();
        {   // cooperative tile load: TS*DD floats = 2048 float4, 32 per thread
            const float4* src = (const float4*)(g_pts + (base + t0) * DD);
            float4* dst = (float4*)sh;
#pragma unroll
            for (int i = 0; i < (TS * DD / 4) / ROWS; i++)
                dst[threadIdx.x + i * ROWS] = src[threadIdx.x + i * ROWS];
#pragma unroll
            for (int i = 0; i < TS / ROWS; i++)
                shsq[threadIdx.x + i * ROWS] = g_sq[base + t0 + threadIdx.x + i * ROWS];
        }
        __syncthreads();

#pragma unroll 2
        for (int j = 0; j < TS; j++) {
            const float4* sp = (const float4*)(sh + j * DD);
            float a0 = 0.f, a1 = 0.f, a2 = 0.f, a3 = 0.f;
#pragma unroll
            for (int i = 0; i < DD / 4; i++) {
                float4 s = sp[i];
                float4 qq = q[i];
                a0 = fmaf(qq.x, s.x, a0);
                a1 = fmaf(qq.y, s.y, a1);
                a2 = fmaf(qq.z, s.z, a2);
                a3 = fmaf(qq.w, s.w, a3);
            }
            float dot = (a0 + a1) + (a2 + a3);
            float d2 = (sqn + shsq[j]) - 2.0f * dot;   // reference formula order
            d2 = fmaxf(d2, 0.0f);                      // clamp like reference

            if (d2 < bd[KK - 1]) {                     // strict <: lower index wins ties
                float v = d2;
                int   vi = t0 + j;
#pragma unroll
                for (int s = 0; s < KK; s++) {         // stable insertion
                    bool sw = v < bd[s];
                    float tv = bd[s];
                    int   ti = bi[s];
                    if (sw) { bd[s] = v; bi[s] = vi; v = tv; vi = ti; }
                }
            }
        }
    }

    // edge_index layout (2, B, N, K): plane 0 = nn_idx, plane 1 = center_idx.
    // Stored as float32 (exactly representable: indices < 8192).
    const size_t o = (base + row) * KK;
#pragma unroll
    for (int i = 0; i < KK; i++) {
        out[o + i] = (float)bi[i];
        out[(size_t)BB * NN * KK + o + i] = (float)row;
    }
}

extern "C" void kernel_launch(void* const* d_in, const int* in_sizes, int n_in,
                              void* d_out, int out_size) {
    // x is the only input with B*D*N elements; never trust positional order.
    int best = 0, best_sz = -1;
    for (int i = 0; i < n_in; i++) {
        if (in_sizes[i] == BB * DD * NN) { best = i; best_sz = in_sizes[i]; break; }
        if (in_sizes[i] > best_sz) { best_sz = in_sizes[i]; best = i; }
    }
    const float* x = (const float*)d_in[best];
    float* out = (float*)d_out;

    normalize_kernel<<<(BB * NN + 255) / 256, 256>>>(x);
    knn_kernel<<<(BB * NN) / ROWS, ROWS>>>(out);
}

// round 9
// speedup vs baseline: 1.2968x; 1.2968x over previous
#include <cuda_runtime.h>

// DenseDilatedKnnGraph: x (4,64,8192,1) fp32 -> edge_index (2,4,8192,9)
// k=9, dilation=1. Output buffer is FLOAT32 (confirmed R8, rel_err 0.0).
//
// R9: GEMM-style register tiling (8x8 per thread) + packed fma.rn.f32x2.
//  - g_ptsT stored [b][dim][point] so both q-tile and c-tile smem loads are
//    conflict-free LDS.128 along the point dimension.
//  - acc packed over row pairs (f32x2); candidate scalar duplicated per k.
//  - per-tile d2 scattered into XOR-swizzled smem (aliases dead c-tile),
//    then per-row linear scan keeps exact reference tie semantics.

#define BB 4
#define DD 64
#define NN 8192
#define KK 9
#define CT 64          // candidates per tile
#define QT 64          // query rows per CTA
#define NTHR 64        // threads per CTA (ty = tid>>3 rows, tx = tid&7 cands)

typedef unsigned long long u64;

__device__ __align__(16) float g_ptsT[(size_t)BB * DD * NN];  // [b][d][n], 8 MB
__device__ float g_sq[BB * NN];

__device__ __forceinline__ u64 ffma2(u64 a, u64 b, u64 c) {
    u64 d;
    asm("fma.rn.f32x2 %0, %1, %2, %3;" : "=l"(d) : "l"(a), "l"(b), "l"(c));
    return d;
}
__device__ __forceinline__ u64 pack2(float v) {
    u64 d;
    asm("mov.b64 %0, {%1, %1};" : "=l"(d) : "f"(v));
    return d;
}
__device__ __forceinline__ float2 unpack2(u64 a) {
    float2 f;
    asm("mov.b64 {%0, %1}, %2;" : "=f"(f.x), "=f"(f.y) : "l"(a));
    return f;
}

// ---------------------------------------------------------------------------
// Stage 1: normalize + transpose-to-[b][d][n]. One thread per point (b,n).
// Both the strided loads and the per-d stores are coalesced across lanes (n).
// ---------------------------------------------------------------------------
__global__ void __launch_bounds__(256) normalize_kernel(const float* __restrict__ x) {
    int idx = blockIdx.x * blockDim.x + threadIdx.x;
    if (idx >= BB * NN) return;
    int b = idx / NN;
    int n = idx - b * NN;
    const float* xb = x + (size_t)b * DD * NN + n;
    float* pb = g_ptsT + (size_t)b * DD * NN + n;

    float v[DD];
    float s = 0.0f;
#pragma unroll
    for (int d = 0; d < DD; d++) {
        v[d] = xb[(size_t)d * NN];
        s += v[d] * v[d];
    }
    float nrm = fmaxf(sqrtf(s), 1e-12f);   // F.normalize eps
    float s2 = 0.0f;
#pragma unroll
    for (int d = 0; d < DD; d++) {
        float xn = v[d] / nrm;             // true division, match reference
        pb[(size_t)d * NN] = xn;
        s2 += xn * xn;                     // reference recomputes sq from normalized
    }
    g_sq[idx] = s2;
}

// ---------------------------------------------------------------------------
// Stage 2: tiled brute-force KNN.
// CTA: 64 threads, 64 query rows, candidate tiles of 64.
// Thread (ty,tx): rows ty*8..ty*8+7, cands tx*8..tx*8+7 within the tile.
// ---------------------------------------------------------------------------
__global__ void __launch_bounds__(NTHR, 6) knn_kernel(float* __restrict__ out) {
    __shared__ __align__(16) float qs[QT * DD];   // [k][row]   16 KB
    __shared__ __align__(16) float cs[CT * DD];   // [k][cand]  16 KB; d2 after compute
    __shared__ float csq[CT];

    const int tid = threadIdx.x;
    const int ty = tid >> 3;          // 0..7  -> row group
    const int tx = tid & 7;           // 0..7  -> cand group
    const int blk = blockIdx.x;       // 0..511
    const int b = blk >> 7;
    const int q0 = (blk & 127) << 6;
    const float* __restrict__ ptsT = g_ptsT + (size_t)b * DD * NN;
    const size_t base = (size_t)b * NN;

    // q tile: qs[k][r] = ptsT[k][q0+r]; flat copy of 1024 float4 (coalesced,
    // conflict-free: lanes write contiguous float4s).
#pragma unroll
    for (int i = 0; i < 16; i++) {
        int f = tid + (i << 6);            // 0..1023
        int k = f >> 4, j4 = f & 15;
        ((float4*)qs)[f] = ((const float4*)(ptsT + (size_t)k * NN + q0))[j4];
    }
    float sqn[8];
#pragma unroll
    for (int rr = 0; rr < 8; rr++) sqn[rr] = g_sq[base + q0 + (ty << 3) + rr];

    float bd[KK];
    int   bi[KK];
#pragma unroll
    for (int i = 0; i < KK; i++) { bd[i] = 3.4e38f; bi[i] = 0; }

    u64 acc[32];                       // [row_pair p 0..3][cand cc 0..7]
#pragma unroll
    for (int i = 0; i < 32; i++) acc[i] = 0ull;

    for (int t0 = 0; t0 < NN; t0 += CT) {
        __syncthreads();               // prev scan done; safe to overwrite cs
#pragma unroll
        for (int i = 0; i < 16; i++) {
            int f = tid + (i << 6);
            int k = f >> 4, j4 = f & 15;
            ((float4*)cs)[f] = ((const float4*)(ptsT + (size_t)k * NN + t0))[j4];
        }
        csq[tid] = g_sq[base + t0 + tid];
        __syncthreads();

        // ---- mainloop: 64 k-steps, 64 MACs (32 FFMA2) per step per thread
#pragma unroll 4
        for (int k = 0; k < DD; k++) {
            const float* qk = qs + (k << 6) + (ty << 3);
            ulonglong2 qA = *(const ulonglong2*)(qk);       // rows +0..3 (2 pairs)
            ulonglong2 qB = *(const ulonglong2*)(qk + 4);   // rows +4..7
            const float* ck = cs + (k << 6) + (tx << 3);
            float4 cA = *(const float4*)(ck);
            float4 cB = *(const float4*)(ck + 4);
            u64 cd[8];
            cd[0] = pack2(cA.x); cd[1] = pack2(cA.y);
            cd[2] = pack2(cA.z); cd[3] = pack2(cA.w);
            cd[4] = pack2(cB.x); cd[5] = pack2(cB.y);
            cd[6] = pack2(cB.z); cd[7] = pack2(cB.w);
#pragma unroll
            for (int c = 0; c < 8; c++) {
                acc[0 * 8 + c] = ffma2(qA.x, cd[c], acc[0 * 8 + c]);
                acc[1 * 8 + c] = ffma2(qA.y, cd[c], acc[1 * 8 + c]);
                acc[2 * 8 + c] = ffma2(qB.x, cd[c], acc[2 * 8 + c]);
                acc[3 * 8 + c] = ffma2(qB.y, cd[c], acc[3 * 8 + c]);
            }
        }
        __syncthreads();               // all reads of cs done

        // ---- epilogue: d2 -> swizzled smem (aliases cs)
        // layout: d2[r,c] at word c*64 + (r ^ (c>>3)); conflict-free for both
        // the (ty,tx) scatter and the row-linear scan.
        float cq[8];
#pragma unroll
        for (int cc = 0; cc < 8; cc++) cq[cc] = csq[(tx << 3) + cc];
#pragma unroll
        for (int p = 0; p < 4; p++) {
            int r0 = (ty << 3) + 2 * p;
#pragma unroll
            for (int cc = 0; cc < 8; cc++) {
                float2 d = unpack2(acc[p * 8 + cc]);
                acc[p * 8 + cc] = 0ull;                  // reset for next tile
                int c = (tx << 3) + cc;                  // c>>3 == tx
                float d2a = fmaxf((sqn[2 * p]     + cq[cc]) - 2.0f * d.x, 0.0f);
                float d2b = fmaxf((sqn[2 * p + 1] + cq[cc]) - 2.0f * d.y, 0.0f);
                cs[(c << 6) + (r0 ^ tx)]       = d2a;
                cs[(c << 6) + ((r0 + 1) ^ tx)] = d2b;
            }
        }
        __syncthreads();

        // ---- scan: thread tid owns query row tid; ascending j keeps exact
        // reference tie order (strict < : lower index wins).
        for (int j = 0; j < CT; j++) {
            float v = cs[(j << 6) + (tid ^ (j >> 3))];
            if (v < bd[KK - 1]) {
                float vv = v;
                int   vi = t0 + j;
#pragma unroll
                for (int s = 0; s < KK; s++) {
                    bool sw = vv < bd[s];
                    float tv = bd[s];
                    int   ti = bi[s];
                    if (sw) { bd[s] = vv; bi[s] = vi; vv = tv; vi = ti; }
                }
            }
        }
    }

    // edge_index (2, B, N, K) as float: plane 0 = nn_idx, plane 1 = center
    const size_t o = (base + q0 + tid) * KK;
#pragma unroll
    for (int i = 0; i < KK; i++) {
        out[o + i] = (float)bi[i];
        out[(size_t)BB * NN * KK + o + i] = (float)(q0 + tid);
    }
}

extern "C" void kernel_launch(void* const* d_in, const int* in_sizes, int n_in,
                              void* d_out, int out_size) {
    // x is the only input with B*D*N elements; never trust positional order.
    int best = 0, best_sz = -1;
    for (int i = 0; i < n_in; i++) {
        if (in_sizes[i] == BB * DD * NN) { best = i; best_sz = in_sizes[i]; break; }
        if (in_sizes[i] > best_sz) { best_sz = in_sizes[i]; best = i; }
    }
    const float* x = (const float*)d_in[best];
    float* out = (float*)d_out;

    normalize_kernel<<<(BB * NN + 255) / 256, 256>>>(x);
    knn_kernel<<<(BB * NN) / QT, NTHR>>>(out);
}